// round 2
// baseline (speedup 1.0000x reference)
#include <cuda_runtime.h>
#include <math.h>

#define NN 50000
#define EE 800000
#define HD 128
#define HSZ (1u<<21)
#define NT 256
#define FULLMASK 0xffffffffu

// ---------------- static device scratch (no allocations allowed) ----------------
__device__ float g_xw[NN*HD];      // GEMM output (pre-propagation features)
__device__ float g_cv[NN*HD];      // conv accumulation buffer
__device__ float g_xa[NN*HD];      // ping
__device__ float g_xb[NN*HD];      // pong
__device__ float g_m0[NN*HD];      // memory[0] (relu conv0)
__device__ float g_m1[NN*HD];
__device__ float g_m2[NN*HD];
__device__ float g_xcat[NN*384];   // concat buffer for up path (stride 256 or 384)
__device__ float g_p1[NN];
__device__ float g_p2[NN];
__device__ float g_deg[NN];
__device__ float g_dinv[4][NN];    // per-topology rsqrt(deg)
__device__ float g_ssum[NN];
__device__ float g_scnt[NN];
__device__ int   g_parent[NN];
__device__ int   g_cl[3][NN];      // cluster labels per level
__device__ float g_s[EE];          // masked edge score (0 if not selected)
__device__ int   g_esrc[4][EE];
__device__ int   g_edst[4][EE];
__device__ float g_eew[4][EE];
__device__ unsigned g_htab[HSZ];
__device__ float g_xw1[NN];        // final scalar gemm out
__device__ float g_o1[NN];         // final conv out

// ---------------- kernels ----------------

__global__ void k_copy_edges0(const int* __restrict__ ei) {
    int e = blockIdx.x*blockDim.x + threadIdx.x;
    if (e >= EE) return;
    g_esrc[0][e] = ei[2*e];
    g_edst[0][e] = ei[2*e+1];
    g_eew[0][e]  = 1.0f;
}

__global__ void k_deg_init() {
    int v = blockIdx.x*blockDim.x + threadIdx.x;
    if (v < NN) g_deg[v] = 2.0f;  // improved GCN: A + 2I
}

__global__ void k_deg_acc(int t) {
    int e = blockIdx.x*blockDim.x + threadIdx.x;
    if (e >= EE) return;
    float w = g_eew[t][e];
    if (w != 0.0f) atomicAdd(&g_deg[g_edst[t][e]], w);
}

__global__ void k_dinv(int t) {
    int v = blockIdx.x*blockDim.x + threadIdx.x;
    if (v < NN) g_dinv[t][v] = rsqrtf(g_deg[v]);
}

// GEMM: g_xw[N,128] = X[N,kin] @ W[kin,128]   (no bias: bias is added in conv_self)
__global__ void k_gemm(const float* __restrict__ X, const float* __restrict__ W, int kin) {
    __shared__ float xs[16*256];
    int row0 = blockIdx.x * 16;
    int c = threadIdx.x;                      // 0..127 = output column
    int tot = 16 * kin;
    for (int i = c; i < tot; i += 128) {
        int r = i / kin, k = i - r*kin;
        int row = row0 + r;
        xs[r*kin + k] = (row < NN) ? X[(size_t)row*kin + k] : 0.0f;
    }
    __syncthreads();
    float acc[16];
#pragma unroll
    for (int r = 0; r < 16; r++) acc[r] = 0.0f;
#pragma unroll 4
    for (int k = 0; k < kin; k++) {
        float w = W[k*HD + c];
#pragma unroll
        for (int r = 0; r < 16; r++) acc[r] += xs[r*kin + k] * w;
    }
#pragma unroll
    for (int r = 0; r < 16; r++) {
        int row = row0 + r;
        if (row < NN) g_xw[row*HD + c] = acc[r];
    }
}

// out[v,f] = 2*dinv^2 * xw[v,f] + b[f]  (self term + bias, initializes g_cv)
__global__ void k_conv_self(int t, const float* __restrict__ b) {
    int i = blockIdx.x*blockDim.x + threadIdx.x;
    if (i >= NN*HD) return;
    int v = i >> 7, f = i & 127;
    float dv = g_dinv[t][v];
    g_cv[i] = 2.0f*dv*dv*g_xw[i] + b[f];
}

// warp per edge: g_cv[dst] += xw[src] * (ew * dinv[src]*dinv[dst])
__global__ void k_conv_edge(int t) {
    int gt = blockIdx.x*blockDim.x + threadIdx.x;
    int e = gt >> 5, lane = gt & 31;
    if (e >= EE) return;
    float w = g_eew[t][e];
    if (w == 0.0f) return;
    int s = g_esrc[t][e], d = g_edst[t][e];
    float norm = w * g_dinv[t][s] * g_dinv[t][d];
    float4 xv = ((const float4*)(g_xw + s*HD))[lane];
    float* o = g_cv + d*HD + lane*4;
    atomicAdd(o+0, xv.x*norm);
    atomicAdd(o+1, xv.y*norm);
    atomicAdd(o+2, xv.z*norm);
    atomicAdd(o+3, xv.w*norm);
}

__global__ void k_relu(float* __restrict__ out) {
    int i = blockIdx.x*blockDim.x + threadIdx.x;
    if (i < NN*HD) out[i] = fmaxf(g_cv[i], 0.0f);
}

// per-node projections p1 = x . Wp[:128], p2 = x . Wp[128:]  (warp per node)
__global__ void k_proj(const float* __restrict__ x, const float* __restrict__ Wp) {
    int gt = blockIdx.x*blockDim.x + threadIdx.x;
    int n = gt >> 5, lane = gt & 31;
    if (n >= NN) return;
    float4 xv = ((const float4*)(x + n*HD))[lane];
    float4 w1 = ((const float4*)Wp)[lane];
    float4 w2 = ((const float4*)(Wp + HD))[lane];
    float a = xv.x*w1.x + xv.y*w1.y + xv.z*w1.z + xv.w*w1.w;
    float b = xv.x*w2.x + xv.y*w2.y + xv.z*w2.z + xv.w*w2.w;
#pragma unroll
    for (int o = 16; o > 0; o >>= 1) {
        a += __shfl_xor_sync(FULLMASK, a, o);
        b += __shfl_xor_sync(FULLMASK, b, o);
    }
    if (lane == 0) { g_p1[n] = a; g_p2[n] = b; }
}

__global__ void k_score(int t, const float* __restrict__ bp) {
    int e = blockIdx.x*blockDim.x + threadIdx.x;
    if (e >= EE) return;
    float w = g_eew[t][e];
    int s = g_esrc[t][e], d = g_edst[t][e];
    float z = g_p1[s] + g_p2[d] + bp[0];
    float sc = 1.0f / (1.0f + expf(-z));
    bool sel = (w > 0.0f) && (s != d) && (sc > 0.5f);
    g_s[e] = sel ? sc : 0.0f;
}

__global__ void k_parent_init() {
    int v = blockIdx.x*blockDim.x + threadIdx.x;
    if (v < NN) g_parent[v] = v;
}

__device__ __forceinline__ int uf_find(int x) {
    volatile int* P = g_parent;
    while (true) {
        int p = P[x];
        if (p == x) return x;
        int gp = P[p];
        if (gp == p) return p;
        P[x] = gp;       // path halving (benign race: gp is an ancestor)
        x = gp;
    }
}

// union by min: link larger root under smaller root -> final root == component min
__global__ void k_union(int t) {
    int e = blockIdx.x*blockDim.x + threadIdx.x;
    if (e >= EE) return;
    if (g_s[e] <= 0.0f) return;
    int ru = uf_find(g_esrc[t][e]);
    int rv = uf_find(g_edst[t][e]);
    while (ru != rv) {
        if (ru < rv) { int tt = ru; ru = rv; rv = tt; }
        int old = atomicCAS(&g_parent[ru], ru, rv);
        if (old == ru) break;
        ru = uf_find(old);
        rv = uf_find(rv);
    }
}

__global__ void k_flatten(int L) {
    int v = blockIdx.x*blockDim.x + threadIdx.x;
    if (v < NN) g_cl[L][v] = uf_find(v);
}

__global__ void k_zero_pool(float* __restrict__ xn) {
    int i = blockIdx.x*blockDim.x + threadIdx.x;
    if (i < NN) { g_ssum[i] = 0.0f; g_scnt[i] = 0.0f; }
    if (i < NN*HD) xn[i] = 0.0f;
}

__global__ void k_seg(int t, int L) {
    int e = blockIdx.x*blockDim.x + threadIdx.x;
    if (e >= EE) return;
    float s = g_s[e];
    if (s <= 0.0f) return;
    int c = g_cl[L][g_esrc[t][e]];
    atomicAdd(&g_ssum[c], s);
    atomicAdd(&g_scnt[c], 1.0f);
}

__global__ void k_nodeacc(int L, const float* __restrict__ x, float* __restrict__ xn) {
    int i = blockIdx.x*blockDim.x + threadIdx.x;
    if (i >= NN*HD) return;
    int v = i >> 7, f = i & 127;
    atomicAdd(&xn[g_cl[L][v]*HD + f], x[i]);
}

__global__ void k_scale(float* __restrict__ xn) {
    int i = blockIdx.x*blockDim.x + threadIdx.x;
    if (i >= NN*HD) return;
    int v = i >> 7;
    float c = g_scnt[v];
    float w = (c > 0.0f) ? g_ssum[v] / fmaxf(c, 1.0f) : 1.0f;
    xn[i] *= w;
}

__global__ void k_hclear() {
    int i = blockIdx.x*blockDim.x + threadIdx.x;
    if (i < (int)HSZ) g_htab[i] = 0xFFFFFFFFu;
}

// contract + dedup via hash of directed pair key = a*NN + b (< 2^32)
__global__ void k_relabel(int tin, int tout, int L) {
    int e = blockIdx.x*blockDim.x + threadIdx.x;
    if (e >= EE) return;
    int ns = 0, nd = 0; float nw = 0.0f;
    float w = g_eew[tin][e];
    if (w > 0.0f) {
        int a = g_cl[L][g_esrc[tin][e]];
        int b = g_cl[L][g_edst[tin][e]];
        if (a != b) {
            unsigned key = (unsigned)a * (unsigned)NN + (unsigned)b;
            unsigned h = (unsigned)(((unsigned long long)key * 2654435761u) >> 11) & (HSZ-1);
            while (true) {
                unsigned old = atomicCAS(&g_htab[h], 0xFFFFFFFFu, key);
                if (old == 0xFFFFFFFFu) { ns = a; nd = b; nw = 1.0f; break; }
                if (old == key) break;  // duplicate
                h = (h + 1) & (HSZ-1);
            }
        }
    }
    g_esrc[tout][e] = ns; g_edst[tout][e] = nd; g_eew[tout][e] = nw;
}

// up-path concat: [mem | (x_in) | x_up[cluster]]  width = 256 or 384
__global__ void k_concat(const float* __restrict__ mem, const float* __restrict__ xup,
                         int L, int width, const float* __restrict__ xin_extra) {
    int i = blockIdx.x*blockDim.x + threadIdx.x;
    if (i >= NN*HD) return;
    int v = i >> 7, f = i & 127;
    float* row = g_xcat + (size_t)v*width;
    row[f] = mem[i];
    int c = g_cl[L][v];
    if (width == 256) {
        row[128 + f] = xup[c*HD + f];
    } else {
        row[128 + f] = xin_extra[i];
        row[256 + f] = xup[c*HD + f];
    }
}

// final projection: xw1[n] = xcat[n,:384] . Wu2   (warp per node)
__global__ void k_dot384(const float* __restrict__ Wu2) {
    int gt = blockIdx.x*blockDim.x + threadIdx.x;
    int n = gt >> 5, lane = gt & 31;
    if (n >= NN) return;
    const float* row = g_xcat + (size_t)n*384;
    float a = 0.0f;
#pragma unroll
    for (int j = 0; j < 12; j++) {
        int k = lane + 32*j;
        a += row[k] * Wu2[k];
    }
#pragma unroll
    for (int o = 16; o > 0; o >>= 1) a += __shfl_xor_sync(FULLMASK, a, o);
    if (lane == 0) g_xw1[n] = a;
}

__global__ void k_conv1_self(const float* __restrict__ bu) {
    int v = blockIdx.x*blockDim.x + threadIdx.x;
    if (v >= NN) return;
    float dv = g_dinv[0][v];
    g_o1[v] = 2.0f*dv*dv*g_xw1[v] + bu[0];
}

__global__ void k_conv1_edge() {
    int e = blockIdx.x*blockDim.x + threadIdx.x;
    if (e >= EE) return;
    float w = g_eew[0][e];
    if (w == 0.0f) return;
    int s = g_esrc[0][e], d = g_edst[0][e];
    atomicAdd(&g_o1[d], g_xw1[s] * w * g_dinv[0][s] * g_dinv[0][d]);
}

__global__ void k_sigmoid(float* __restrict__ out) {
    int v = blockIdx.x*blockDim.x + threadIdx.x;
    if (v < NN) out[v] = 1.0f / (1.0f + expf(-g_o1[v]));
}

// ---------------- host orchestration ----------------

extern "C" void kernel_launch(void* const* d_in, const int* in_sizes, int n_in,
                              void* d_out, int out_size) {
    (void)in_sizes; (void)n_in; (void)out_size;
    const float* x_in = (const float*)d_in[0];
    const int*   ei   = (const int*)d_in[1];
    const float* Wd[4] = {(const float*)d_in[3],(const float*)d_in[5],(const float*)d_in[7],(const float*)d_in[9]};
    const float* bd[4] = {(const float*)d_in[4],(const float*)d_in[6],(const float*)d_in[8],(const float*)d_in[10]};
    const float* Wp[3] = {(const float*)d_in[11],(const float*)d_in[13],(const float*)d_in[15]};
    const float* bp[3] = {(const float*)d_in[12],(const float*)d_in[14],(const float*)d_in[16]};
    const float* Wu[3] = {(const float*)d_in[17],(const float*)d_in[19],(const float*)d_in[21]};
    const float* bu[3] = {(const float*)d_in[18],(const float*)d_in[20],(const float*)d_in[22]};
    float* out = (float*)d_out;

    void* pv;
    float *p_xa, *p_xb, *p_cv, *p_m0, *p_m1, *p_m2, *p_xcat;
    cudaGetSymbolAddress(&pv, g_xa);   p_xa   = (float*)pv;
    cudaGetSymbolAddress(&pv, g_xb);   p_xb   = (float*)pv;
    cudaGetSymbolAddress(&pv, g_cv);   p_cv   = (float*)pv;
    cudaGetSymbolAddress(&pv, g_m0);   p_m0   = (float*)pv;
    cudaGetSymbolAddress(&pv, g_m1);   p_m1   = (float*)pv;
    cudaGetSymbolAddress(&pv, g_m2);   p_m2   = (float*)pv;
    cudaGetSymbolAddress(&pv, g_xcat); p_xcat = (float*)pv;

    const int gN  = (NN + NT - 1) / NT;
    const int gNF = (NN*HD + NT - 1) / NT;
    const int gE  = (EE + NT - 1) / NT;
    const int gEw = (EE*32 + NT - 1) / NT;
    const int gNw = (NN*32 + NT - 1) / NT;
    const int gG  = (NN + 15) / 16;
    const int gH  = ((int)HSZ + NT - 1) / NT;

    k_copy_edges0<<<gE, NT>>>(ei);

    // ---- DOWN levels ----
    const float* Xin[3]  = { x_in, p_xa, p_xb };
    float*       memb[3] = { p_m0, p_m1, p_m2 };
    float*       xout[3] = { p_xa, p_xb, p_xa };
    for (int i = 0; i < 3; i++) {
        int t = i;
        k_deg_init<<<gN, NT>>>();
        k_deg_acc<<<gE, NT>>>(t);
        k_dinv<<<gN, NT>>>(t);
        k_gemm<<<gG, 128>>>(Xin[i], Wd[i], 128);
        k_conv_self<<<gNF, NT>>>(t, bd[i]);
        k_conv_edge<<<gEw, NT>>>(t);
        k_relu<<<gNF, NT>>>(memb[i]);
        // pooling
        k_proj<<<gNw, NT>>>(memb[i], Wp[i]);
        k_score<<<gE, NT>>>(t, bp[i]);
        k_parent_init<<<gN, NT>>>();
        k_union<<<gE, NT>>>(t);
        k_flatten<<<gN, NT>>>(i);
        k_zero_pool<<<gNF, NT>>>(xout[i]);
        k_seg<<<gE, NT>>>(t, i);
        k_nodeacc<<<gNF, NT>>>(i, memb[i], xout[i]);
        k_scale<<<gNF, NT>>>(xout[i]);
        k_hclear<<<gH, NT>>>();
        k_relabel<<<gE, NT>>>(t, t + 1, i);
    }

    // ---- BOTTOM conv (topology 3, no relu; result stays in g_cv) ----
    k_deg_init<<<gN, NT>>>();
    k_deg_acc<<<gE, NT>>>(3);
    k_dinv<<<gN, NT>>>(3);
    k_gemm<<<gG, 128>>>(p_xa, Wd[3], 128);
    k_conv_self<<<gNF, NT>>>(3, bd[3]);
    k_conv_edge<<<gEw, NT>>>(3);

    // ---- UP 0 : level L=2, topology 2 ----
    k_concat<<<gNF, NT>>>(p_m2, p_cv, 2, 256, (const float*)0);
    k_gemm<<<gG, 128>>>(p_xcat, Wu[0], 256);
    k_conv_self<<<gNF, NT>>>(2, bu[0]);
    k_conv_edge<<<gEw, NT>>>(2);
    k_relu<<<gNF, NT>>>(p_xa);

    // ---- UP 1 : level L=1, topology 1 ----
    k_concat<<<gNF, NT>>>(p_m1, p_xa, 1, 256, (const float*)0);
    k_gemm<<<gG, 128>>>(p_xcat, Wu[1], 256);
    k_conv_self<<<gNF, NT>>>(1, bu[1]);
    k_conv_edge<<<gEw, NT>>>(1);
    k_relu<<<gNF, NT>>>(p_xb);

    // ---- UP 2 : level L=0, topology 0, output dim 1 ----
    k_concat<<<gNF, NT>>>(p_m0, p_xb, 0, 384, x_in);
    k_dot384<<<gNw, NT>>>(Wu[2]);
    k_conv1_self<<<gN, NT>>>(bu[2]);
    k_conv1_edge<<<gE, NT>>>();
    k_sigmoid<<<gN, NT>>>(out);
}

// round 3
// speedup vs baseline: 1.1818x; 1.1818x over previous
#include <cuda_runtime.h>
#include <math.h>

#define NN 50000
#define EE 800000
#define HD 128
#define HSZ (1u<<21)
#define NT 256
#define FULLMASK 0xffffffffu
#define NB 196   // (NN+255)/256

// ---------------- static device scratch ----------------
__device__ float g_xw[NN*HD];
__device__ float g_cv[NN*HD];
__device__ float g_xa[NN*HD];
__device__ float g_xb[NN*HD];
__device__ float g_m0[NN*HD];
__device__ float g_m1[NN*HD];
__device__ float g_m2[NN*HD];
__device__ float g_xcat[NN*384];
__device__ float g_p1[NN];
__device__ float g_p2[NN];
__device__ float g_dinv[4][NN];
__device__ float g_ssum[NN];
__device__ float g_scnt[NN];
__device__ int   g_parent[NN];
__device__ int   g_cl[3][NN];
__device__ float g_s[EE];
__device__ int   g_esrc[4][EE];
__device__ int   g_edst[4][EE];
__device__ float g_eew[4][EE];
__device__ unsigned g_htab[HSZ];
__device__ float g_xw1[NN];
// CSR (per topology, persistent across down/up passes)
__device__ int   g_coff[4][NN];
__device__ int   g_ccnt[4][NN];
__device__ int   g_csrc[4][EE];
__device__ float g_cnorm[4][EE];
__device__ int   g_cnt[NN];
__device__ int   g_wcur[NN];
__device__ int   g_bsum[256];
__device__ int   g_boff[256];

// ---------------- kernels ----------------

__global__ void k_copy_edges0(const int* __restrict__ ei) {
    int e = blockIdx.x*blockDim.x + threadIdx.x;
    if (e >= EE) return;
    g_esrc[0][e] = ei[2*e];
    g_edst[0][e] = ei[2*e+1];
    g_eew[0][e]  = 1.0f;
}

__global__ void k_cnt_zero() {
    int v = blockIdx.x*blockDim.x + threadIdx.x;
    if (v < NN) g_cnt[v] = 0;
}

__global__ void k_cnt(int t) {
    int e = blockIdx.x*blockDim.x + threadIdx.x;
    if (e >= EE) return;
    if (g_eew[t][e] > 0.0f) atomicAdd(&g_cnt[g_edst[t][e]], 1);
}

__global__ void k_scan1(int t) {
    __shared__ int sh[256];
    int tx = threadIdx.x;
    int v = blockIdx.x*256 + tx;
    int c = (v < NN) ? g_cnt[v] : 0;
    sh[tx] = c; __syncthreads();
    int val = c;
    for (int o = 1; o < 256; o <<= 1) {
        int y = (tx >= o) ? sh[tx-o] : 0;
        __syncthreads();
        val += y; sh[tx] = val;
        __syncthreads();
    }
    if (v < NN) g_coff[t][v] = val - c;       // exclusive within block
    if (tx == 255) g_bsum[blockIdx.x] = val;  // block total
}

__global__ void k_scan2() {
    __shared__ int sh[256];
    int tx = threadIdx.x;
    int c = (tx < NB) ? g_bsum[tx] : 0;
    sh[tx] = c; __syncthreads();
    int val = c;
    for (int o = 1; o < 256; o <<= 1) {
        int y = (tx >= o) ? sh[tx-o] : 0;
        __syncthreads();
        val += y; sh[tx] = val;
        __syncthreads();
    }
    g_boff[tx] = val - c;  // exclusive block offsets
}

__global__ void k_scan3(int t) {
    int v = blockIdx.x*blockDim.x + threadIdx.x;
    if (v >= NN) return;
    int c = g_cnt[v];
    int o = g_coff[t][v] + g_boff[v >> 8];
    g_coff[t][v] = o;
    g_wcur[v]    = o;
    g_ccnt[t][v] = c;
    g_dinv[t][v] = rsqrtf(2.0f + (float)c);  // improved GCN: deg = 2 + sum(ew)
}

__global__ void k_fill(int t) {
    int e = blockIdx.x*blockDim.x + threadIdx.x;
    if (e >= EE) return;
    float w = g_eew[t][e];
    if (w <= 0.0f) return;
    int s = g_esrc[t][e], d = g_edst[t][e];
    int pos = atomicAdd(&g_wcur[d], 1);
    g_csrc[t][pos]  = s;
    g_cnorm[t][pos] = w * g_dinv[t][s] * g_dinv[t][d];
}

// register-blocked GEMM: g_xw[N,128] = X[N,kin] @ W[kin,128]
__global__ void __launch_bounds__(256) k_gemm2(const float* __restrict__ X,
                                               const float* __restrict__ W, int kin) {
    __shared__ float Xs[32][65];    // [k][row]
    __shared__ float Ws[32][128];   // [k][col]
    int row0 = blockIdx.x * 64;
    int tid = threadIdx.x;
    int cid = tid & 31;   // cols 4*cid .. 4*cid+3
    int rid = tid >> 5;   // rows rid + 8*r
    float acc[8][4];
#pragma unroll
    for (int r = 0; r < 8; r++) { acc[r][0]=0.f; acc[r][1]=0.f; acc[r][2]=0.f; acc[r][3]=0.f; }
    for (int k0 = 0; k0 < kin; k0 += 32) {
        for (int i = tid; i < 64*32; i += 256) {
            int r = i >> 5, kk = i & 31;
            int row = row0 + r;
            Xs[kk][r] = (row < NN) ? X[(size_t)row*kin + k0 + kk] : 0.0f;
        }
        for (int i = tid; i < 32*128; i += 256) {
            int kk = i >> 7, c = i & 127;
            Ws[kk][c] = W[(size_t)(k0+kk)*HD + c];
        }
        __syncthreads();
#pragma unroll
        for (int kk = 0; kk < 32; kk++) {
            float4 w = *(const float4*)&Ws[kk][cid*4];
            float xr[8];
#pragma unroll
            for (int r = 0; r < 8; r++) xr[r] = Xs[kk][rid + 8*r];
#pragma unroll
            for (int r = 0; r < 8; r++) {
                acc[r][0] += xr[r]*w.x; acc[r][1] += xr[r]*w.y;
                acc[r][2] += xr[r]*w.z; acc[r][3] += xr[r]*w.w;
            }
        }
        __syncthreads();
    }
#pragma unroll
    for (int r = 0; r < 8; r++) {
        int row = row0 + rid + 8*r;
        if (row < NN)
            *(float4*)&g_xw[row*HD + cid*4] = make_float4(acc[r][0],acc[r][1],acc[r][2],acc[r][3]);
    }
}

// CSR gather conv: out[v] = sum_in xw[src]*norm + 2*dinv^2*xw[v] + b  (optional relu)
__global__ void k_conv_gather(int t, const float* __restrict__ b,
                              float* __restrict__ out, int dorelu) {
    int gt = blockIdx.x*blockDim.x + threadIdx.x;
    int v = gt >> 5, lane = gt & 31;
    if (v >= NN) return;
    int off = g_coff[t][v], n = g_ccnt[t][v];
    float4 acc = make_float4(0.f,0.f,0.f,0.f);
    for (int i = 0; i < n; i++) {
        int s   = g_csrc[t][off+i];
        float nm = g_cnorm[t][off+i];
        float4 xv = ((const float4*)(g_xw + (size_t)s*HD))[lane];
        acc.x += xv.x*nm; acc.y += xv.y*nm; acc.z += xv.z*nm; acc.w += xv.w*nm;
    }
    float dv = g_dinv[t][v];
    float sc = 2.0f*dv*dv;
    float4 xs = ((const float4*)(g_xw + (size_t)v*HD))[lane];
    float4 bb = ((const float4*)b)[lane];
    float4 o;
    o.x = acc.x + sc*xs.x + bb.x;
    o.y = acc.y + sc*xs.y + bb.y;
    o.z = acc.z + sc*xs.z + bb.z;
    o.w = acc.w + sc*xs.w + bb.w;
    if (dorelu) {
        o.x = fmaxf(o.x,0.f); o.y = fmaxf(o.y,0.f);
        o.z = fmaxf(o.z,0.f); o.w = fmaxf(o.w,0.f);
    }
    ((float4*)(out + (size_t)v*HD))[lane] = o;
}

__global__ void k_proj(const float* __restrict__ x, const float* __restrict__ Wp) {
    int gt = blockIdx.x*blockDim.x + threadIdx.x;
    int n = gt >> 5, lane = gt & 31;
    if (n >= NN) return;
    float4 xv = ((const float4*)(x + (size_t)n*HD))[lane];
    float4 w1 = ((const float4*)Wp)[lane];
    float4 w2 = ((const float4*)(Wp + HD))[lane];
    float a = xv.x*w1.x + xv.y*w1.y + xv.z*w1.z + xv.w*w1.w;
    float b = xv.x*w2.x + xv.y*w2.y + xv.z*w2.z + xv.w*w2.w;
#pragma unroll
    for (int o = 16; o > 0; o >>= 1) {
        a += __shfl_xor_sync(FULLMASK, a, o);
        b += __shfl_xor_sync(FULLMASK, b, o);
    }
    if (lane == 0) { g_p1[n] = a; g_p2[n] = b; }
}

__global__ void k_score(int t, const float* __restrict__ bp) {
    int e = blockIdx.x*blockDim.x + threadIdx.x;
    if (e >= EE) return;
    float w = g_eew[t][e];
    int s = g_esrc[t][e], d = g_edst[t][e];
    float z = g_p1[s] + g_p2[d] + bp[0];
    float sc = 1.0f / (1.0f + expf(-z));
    bool sel = (w > 0.0f) && (s != d) && (sc > 0.5f);
    g_s[e] = sel ? sc : 0.0f;
}

__global__ void k_parent_init() {
    int v = blockIdx.x*blockDim.x + threadIdx.x;
    if (v < NN) g_parent[v] = v;
}

__device__ __forceinline__ int uf_find(int x) {
    volatile int* P = g_parent;
    while (true) {
        int p = P[x];
        if (p == x) return x;
        int gp = P[p];
        if (gp == p) return p;
        P[x] = gp;
        x = gp;
    }
}

__global__ void k_union(int t) {
    int e = blockIdx.x*blockDim.x + threadIdx.x;
    if (e >= EE) return;
    if (g_s[e] <= 0.0f) return;
    int ru = uf_find(g_esrc[t][e]);
    int rv = uf_find(g_edst[t][e]);
    while (ru != rv) {
        if (ru < rv) { int tt = ru; ru = rv; rv = tt; }
        int old = atomicCAS(&g_parent[ru], ru, rv);
        if (old == ru) break;
        ru = uf_find(old);
        rv = uf_find(rv);
    }
}

__global__ void k_flatten(int L) {
    int v = blockIdx.x*blockDim.x + threadIdx.x;
    if (v < NN) g_cl[L][v] = uf_find(v);
}

__global__ void k_zero_pool(float* __restrict__ xn) {
    int i = blockIdx.x*blockDim.x + threadIdx.x;
    if (i < NN) { g_ssum[i] = 0.0f; g_scnt[i] = 0.0f; }
    if (i < NN*HD) xn[i] = 0.0f;
}

// warp-aggregated segment sum of edge scores by source-cluster
__global__ void k_seg(int t, int L) {
    int e = blockIdx.x*blockDim.x + threadIdx.x;
    int lane = threadIdx.x & 31;
    float s = 0.0f; int c = -1;
    if (e < EE) {
        float sv = g_s[e];
        if (sv > 0.0f) { s = sv; c = g_cl[L][g_esrc[t][e]]; }
    }
    unsigned m = __match_any_sync(FULLMASK, c);
    int leader = __ffs(m) - 1;
    float tot = 0.0f;
#pragma unroll
    for (int j = 0; j < 32; j++) {
        float os = __shfl_sync(FULLMASK, s, j);
        int   oc = __shfl_sync(FULLMASK, c, j);
        if (lane == leader && c >= 0 && oc == c) tot += os;
    }
    if (lane == leader && c >= 0) {
        atomicAdd(&g_ssum[c], tot);
        atomicAdd(&g_scnt[c], (float)__popc(m));
    }
}

__global__ void k_nodeacc(int L, const float* __restrict__ x, float* __restrict__ xn) {
    int i = blockIdx.x*blockDim.x + threadIdx.x;
    if (i >= NN*32) return;
    int v = i >> 5, f4 = i & 31;
    float4 val = ((const float4*)(x + (size_t)v*HD))[f4];
    atomicAdd(((float4*)(xn + (size_t)g_cl[L][v]*HD)) + f4, val);
}

__global__ void k_scale(float* __restrict__ xn) {
    int i = blockIdx.x*blockDim.x + threadIdx.x;
    if (i >= NN*HD) return;
    int v = i >> 7;
    float c = g_scnt[v];
    float w = (c > 0.0f) ? g_ssum[v] / fmaxf(c, 1.0f) : 1.0f;
    xn[i] *= w;
}

__global__ void k_hclear() {
    int i = blockIdx.x*blockDim.x + threadIdx.x;
    if (i < (int)HSZ) g_htab[i] = 0xFFFFFFFFu;
}

__global__ void k_relabel(int tin, int tout, int L) {
    int e = blockIdx.x*blockDim.x + threadIdx.x;
    if (e >= EE) return;
    int ns = 0, nd = 0; float nw = 0.0f;
    float w = g_eew[tin][e];
    if (w > 0.0f) {
        int a = g_cl[L][g_esrc[tin][e]];
        int b = g_cl[L][g_edst[tin][e]];
        if (a != b) {
            unsigned key = (unsigned)a * (unsigned)NN + (unsigned)b;
            unsigned h = (unsigned)(((unsigned long long)key * 2654435761u) >> 11) & (HSZ-1);
            while (true) {
                unsigned old = atomicCAS(&g_htab[h], 0xFFFFFFFFu, key);
                if (old == 0xFFFFFFFFu) { ns = a; nd = b; nw = 1.0f; break; }
                if (old == key) break;
                h = (h + 1) & (HSZ-1);
            }
        }
    }
    g_esrc[tout][e] = ns; g_edst[tout][e] = nd; g_eew[tout][e] = nw;
}

__global__ void k_concat(const float* __restrict__ mem, const float* __restrict__ xup,
                         int L, int width, const float* __restrict__ xin_extra) {
    int i = blockIdx.x*blockDim.x + threadIdx.x;
    if (i >= NN*HD) return;
    int v = i >> 7, f = i & 127;
    float* row = g_xcat + (size_t)v*width;
    row[f] = mem[i];
    int c = g_cl[L][v];
    if (width == 256) {
        row[128 + f] = xup[(size_t)c*HD + f];
    } else {
        row[128 + f] = xin_extra[i];
        row[256 + f] = xup[(size_t)c*HD + f];
    }
}

__global__ void k_dot384(const float* __restrict__ Wu2) {
    int gt = blockIdx.x*blockDim.x + threadIdx.x;
    int n = gt >> 5, lane = gt & 31;
    if (n >= NN) return;
    const float* row = g_xcat + (size_t)n*384;
    float a = 0.0f;
#pragma unroll
    for (int j = 0; j < 12; j++) {
        int k = lane + 32*j;
        a += row[k] * Wu2[k];
    }
#pragma unroll
    for (int o = 16; o > 0; o >>= 1) a += __shfl_xor_sync(FULLMASK, a, o);
    if (lane == 0) g_xw1[n] = a;
}

// final scalar conv on topology 0 (gather) + sigmoid, fused
__global__ void k_conv1(const float* __restrict__ bu, float* __restrict__ out) {
    int gt = blockIdx.x*blockDim.x + threadIdx.x;
    int v = gt >> 5, lane = gt & 31;
    if (v >= NN) return;
    int off = g_coff[0][v], n = g_ccnt[0][v];
    float acc = 0.0f;
    for (int i = lane; i < n; i += 32)
        acc += g_xw1[g_csrc[0][off+i]] * g_cnorm[0][off+i];
#pragma unroll
    for (int o = 16; o > 0; o >>= 1) acc += __shfl_xor_sync(FULLMASK, acc, o);
    if (lane == 0) {
        float dv = g_dinv[0][v];
        float z = acc + 2.0f*dv*dv*g_xw1[v] + bu[0];
        out[v] = 1.0f / (1.0f + expf(-z));
    }
}

// ---------------- host orchestration ----------------

extern "C" void kernel_launch(void* const* d_in, const int* in_sizes, int n_in,
                              void* d_out, int out_size) {
    (void)in_sizes; (void)n_in; (void)out_size;
    const float* x_in = (const float*)d_in[0];
    const int*   ei   = (const int*)d_in[1];
    const float* Wd[4] = {(const float*)d_in[3],(const float*)d_in[5],(const float*)d_in[7],(const float*)d_in[9]};
    const float* bd[4] = {(const float*)d_in[4],(const float*)d_in[6],(const float*)d_in[8],(const float*)d_in[10]};
    const float* Wp[3] = {(const float*)d_in[11],(const float*)d_in[13],(const float*)d_in[15]};
    const float* bp[3] = {(const float*)d_in[12],(const float*)d_in[14],(const float*)d_in[16]};
    const float* Wu[3] = {(const float*)d_in[17],(const float*)d_in[19],(const float*)d_in[21]};
    const float* bu[3] = {(const float*)d_in[18],(const float*)d_in[20],(const float*)d_in[22]};
    float* out = (float*)d_out;

    void* pv;
    float *p_xa, *p_xb, *p_cv, *p_m0, *p_m1, *p_m2, *p_xcat;
    cudaGetSymbolAddress(&pv, g_xa);   p_xa   = (float*)pv;
    cudaGetSymbolAddress(&pv, g_xb);   p_xb   = (float*)pv;
    cudaGetSymbolAddress(&pv, g_cv);   p_cv   = (float*)pv;
    cudaGetSymbolAddress(&pv, g_m0);   p_m0   = (float*)pv;
    cudaGetSymbolAddress(&pv, g_m1);   p_m1   = (float*)pv;
    cudaGetSymbolAddress(&pv, g_m2);   p_m2   = (float*)pv;
    cudaGetSymbolAddress(&pv, g_xcat); p_xcat = (float*)pv;

    const int gN  = (NN + NT - 1) / NT;
    const int gNF = (NN*HD + NT - 1) / NT;
    const int gN4 = (NN*32 + NT - 1) / NT;
    const int gE  = (EE + NT - 1) / NT;
    const int gNw = (NN*32 + NT - 1) / NT;
    const int gG  = (NN + 63) / 64;
    const int gH  = ((int)HSZ + NT - 1) / NT;

    k_copy_edges0<<<gE, NT>>>(ei);

    const float* Xin[3]  = { x_in, p_xa, p_xb };
    float*       memb[3] = { p_m0, p_m1, p_m2 };
    float*       xout[3] = { p_xa, p_xb, p_xa };
    for (int i = 0; i < 3; i++) {
        int t = i;
        // CSR build (gemm interleaved after scan2 so ncu -s5 profiles it at i=0)
        k_cnt_zero<<<gN, NT>>>();
        k_cnt<<<gE, NT>>>(t);
        k_scan1<<<NB, 256>>>(t);
        k_scan2<<<1, 256>>>();
        k_gemm2<<<gG, 256>>>(Xin[i], Wd[i], 128);
        k_scan3<<<gN, NT>>>(t);
        k_fill<<<gE, NT>>>(t);
        k_conv_gather<<<gNw, NT>>>(t, bd[i], memb[i], 1);
        // pooling
        k_proj<<<gNw, NT>>>(memb[i], Wp[i]);
        k_score<<<gE, NT>>>(t, bp[i]);
        k_parent_init<<<gN, NT>>>();
        k_union<<<gE, NT>>>(t);
        k_flatten<<<gN, NT>>>(i);
        k_zero_pool<<<gNF, NT>>>(xout[i]);
        k_seg<<<gE, NT>>>(t, i);
        k_nodeacc<<<gN4, NT>>>(i, memb[i], xout[i]);
        k_scale<<<gNF, NT>>>(xout[i]);
        k_hclear<<<gH, NT>>>();
        k_relabel<<<gE, NT>>>(t, t + 1, i);
    }

    // ---- bottom conv (topology 3, no relu) ----
    k_cnt_zero<<<gN, NT>>>();
    k_cnt<<<gE, NT>>>(3);
    k_scan1<<<NB, 256>>>(3);
    k_scan2<<<1, 256>>>();
    k_gemm2<<<gG, 256>>>(p_xa, Wd[3], 128);
    k_scan3<<<gN, NT>>>(3);
    k_fill<<<gE, NT>>>(3);
    k_conv_gather<<<gNw, NT>>>(3, bd[3], p_cv, 0);

    // ---- UP 0 : level L=2, topology 2 ----
    k_concat<<<gNF, NT>>>(p_m2, p_cv, 2, 256, (const float*)0);
    k_gemm2<<<gG, 256>>>(p_xcat, Wu[0], 256);
    k_conv_gather<<<gNw, NT>>>(2, bu[0], p_xa, 1);

    // ---- UP 1 : level L=1, topology 1 ----
    k_concat<<<gNF, NT>>>(p_m1, p_xa, 1, 256, (const float*)0);
    k_gemm2<<<gG, 256>>>(p_xcat, Wu[1], 256);
    k_conv_gather<<<gNw, NT>>>(1, bu[1], p_xb, 1);

    // ---- UP 2 : level L=0, topology 0, output dim 1 ----
    k_concat<<<gNF, NT>>>(p_m0, p_xb, 0, 384, x_in);
    k_dot384<<<gNw, NT>>>(Wu[2]);
    k_conv1<<<gNw, NT>>>(bu[2], out);
}